// round 1
// baseline (speedup 1.0000x reference)
#include <cuda_runtime.h>
#include <cstdint>
#include <cstddef>

// LSTM encoder: B=128, T=2048, I=64, H=128
// Phase 1: x_proj[b,t,g] = input[b,t,:] . W_ih[g,:] + b_ih[g] + b_hh[g]   (parallel)
// Phase 2: per-batch-row sequential LSTM recurrence, 1 CTA per batch row (128 CTAs)
//
// Output layout (tuple flatten): [0 : B*H) = h_last ; [B*H : B*H + B*T*H) = encoded

constexpr int B = 128;
constexpr int T = 2048;
constexpr int I = 64;
constexpr int H = 128;
constexpr int G = 4 * H;          // 512 gate outputs
constexpr int KREG = 88;          // k-values of W_hh kept in registers per thread
constexpr int KSM  = H - KREG;    // 40 k-values in shared memory
constexpr int NPAIR_REG = KREG / 2;   // 44 f32x2 pairs
constexpr int KSM4 = KSM / 4;         // 10 float4 groups

// 512 MB scratch for x_proj (device-global: allocation APIs are banned)
__device__ float g_xp[(size_t)B * T * G];

__device__ __forceinline__ void fma2(unsigned long long& d,
                                     unsigned long long a,
                                     unsigned long long b) {
    // packed 2x fp32 FMA — ptxas never auto-generates FFMA2; PTX-only path.
    asm("fma.rn.f32x2 %0, %1, %2, %0;" : "+l"(d) : "l"(a), "l"(b));
}

__device__ __forceinline__ float pair_sum(unsigned long long v) {
    unsigned lo = (unsigned)v;
    unsigned hi = (unsigned)(v >> 32);
    return __uint_as_float(lo) + __uint_as_float(hi);
}

// ---------------------------------------------------------------------------
// Kernel 1: x_proj. One block = 64 flattened (b,t) rows. thread = gate column.
// W_ih row (64 f32 = 32 pairs) lives in registers; input tile broadcast via smem.
// ---------------------------------------------------------------------------
__global__ void __launch_bounds__(512) xproj_kernel(
    const float* __restrict__ in,     // [B*T, I]
    const float* __restrict__ Wih,    // [G, I]
    const float* __restrict__ bih,    // [G]
    const float* __restrict__ bhh)    // [G]
{
    __shared__ float in_s[64 * I];    // 16 KB
    const int tid = threadIdx.x;
    const size_t row0 = (size_t)blockIdx.x * 64;

    // Load 64x64 input tile (4096 floats = 1024 float4, 2 per thread)
    {
        const float4* src = (const float4*)(in + row0 * I);
        float4* dst = (float4*)in_s;
        dst[tid]       = src[tid];
        dst[tid + 512] = src[tid + 512];
    }

    // W_ih row for this gate column into registers (32 f32x2 pairs)
    unsigned long long w2[32];
    {
        const unsigned long long* wrow =
            (const unsigned long long*)(Wih + (size_t)tid * I);
#pragma unroll
        for (int i = 0; i < 32; i++) w2[i] = wrow[i];
    }
    const float bias = bih[tid] + bhh[tid];
    __syncthreads();

    float* outp = g_xp + row0 * G + tid;
#pragma unroll 4
    for (int r = 0; r < 64; r++) {
        const unsigned long long* ip = (const unsigned long long*)(in_s + r * I);
        unsigned long long acc = 0ull;   // packed {0.f, 0.f}
#pragma unroll
        for (int k = 0; k < 32; k++) fma2(acc, w2[k], ip[k]);
        outp[(size_t)r * G] = pair_sum(acc) + bias;
    }
}

// ---------------------------------------------------------------------------
// Kernel 2: recurrence. 1 CTA per batch row, 512 threads (thread = gate output g).
// W_hh[g, 0:88] in registers, W_hh[g, 88:128] in smem (k-major float4 layout).
// Per step: all threads compute gate preactivation; threads 0..127 do the cell
// update, write h to smem + gmem. Two __syncthreads per step.
// ---------------------------------------------------------------------------
__global__ void __launch_bounds__(512, 1) lstm_kernel(
    const float* __restrict__ h0,    // [B, H]
    const float* __restrict__ c0,    // [B, H]
    const float* __restrict__ Whh,   // [G, H]
    float* __restrict__ out)         // [B*H + B*T*H]
{
    extern __shared__ float smem[];
    float* Ws     = smem;                 // KSM4 groups * G * 4 floats = 20480 f (80 KB)
    float* h_s    = smem + KSM * G;       // 128 floats (16B aligned)
    float* gate_s = h_s + H;              // 512 floats

    const int g = threadIdx.x;            // gate output index 0..511
    const int b = blockIdx.x;             // batch row

    // Fill smem weight slice: Ws4[k4][g] = W_hh[g][KREG + 4*k4 .. +3]
    {
        const float4* wq = (const float4*)(Whh + (size_t)g * H + KREG);
        float4* wsq = (float4*)Ws;
#pragma unroll
        for (int k4 = 0; k4 < KSM4; k4++) wsq[k4 * G + g] = wq[k4];
    }

    // Register weight slice: 44 f32x2 pairs
    unsigned long long wr[NPAIR_REG];
    {
        const unsigned long long* wrow =
            (const unsigned long long*)(Whh + (size_t)g * H);
#pragma unroll
        for (int i = 0; i < NPAIR_REG; i++) wr[i] = wrow[i];
    }

    float c = 0.f;
    if (g < H) {
        c = c0[b * H + g];
        h_s[g] = h0[b * H + g];
    }

    // x_proj stream for this (b, g), prefetch depth 2
    const float* xp = g_xp + (size_t)b * T * G + g;
    float xc = xp[0];
    float xn = xp[G];

    __syncthreads();

    float* enc = out + (size_t)B * H + (size_t)b * T * H;

    for (int t = 0; t < T; t++) {
        // prefetch x_proj for t+2 (issued early, consumed ~2 steps later)
        float xf = 0.f;
        if (t + 2 < T) xf = xp[(size_t)(t + 2) * G];

        unsigned long long acc = 0ull;
        const ulonglong2* h2 = (const ulonglong2*)h_s;

        // register-weight portion: k in [0, 88)
#pragma unroll
        for (int q = 0; q < NPAIR_REG / 2; q++) {   // 22 quads of h
            ulonglong2 hv = h2[q];
            fma2(acc, wr[2 * q],     hv.x);
            fma2(acc, wr[2 * q + 1], hv.y);
        }
        // smem-weight portion: k in [88, 128)
        {
            const ulonglong2* ws2 = (const ulonglong2*)Ws;
#pragma unroll
            for (int q = 0; q < KSM4; q++) {
                ulonglong2 hv = h2[KREG / 4 + q];
                ulonglong2 wv = ws2[q * G + g];
                fma2(acc, wv.x, hv.x);
                fma2(acc, wv.y, hv.y);
            }
        }

        gate_s[g] = pair_sum(acc) + xc;
        xc = xn; xn = xf;
        __syncthreads();

        if (g < H) {
            float gi = gate_s[g];
            float gf = gate_s[H + g];
            float gg = gate_s[2 * H + g];
            float go = gate_s[3 * H + g];
            float ig = 1.f / (1.f + __expf(-gi));
            float fg = 1.f / (1.f + __expf(-gf));
            float og = 1.f / (1.f + __expf(-go));
            float gt = tanhf(gg);
            c = fg * c + ig * gt;
            float hn = og * tanhf(c);
            h_s[g] = hn;
            enc[(size_t)t * H + g] = hn;
            if (t == T - 1) out[b * H + g] = hn;
        }
        __syncthreads();
    }
}

// ---------------------------------------------------------------------------
extern "C" void kernel_launch(void* const* d_in, const int* in_sizes, int n_in,
                              void* d_out, int out_size) {
    const float* input = (const float*)d_in[0];   // [B, T, I]
    const float* h0    = (const float*)d_in[1];   // [B, H]
    const float* c0    = (const float*)d_in[2];   // [B, H]
    const float* Wih   = (const float*)d_in[3];   // [4H, I]
    const float* Whh   = (const float*)d_in[4];   // [4H, H]
    const float* bih   = (const float*)d_in[5];   // [4H]
    const float* bhh   = (const float*)d_in[6];   // [4H]
    float* out = (float*)d_out;

    constexpr int SMEM2 = (KSM * G + H + G) * (int)sizeof(float);  // 84480 B
    cudaFuncSetAttribute(lstm_kernel,
                         cudaFuncAttributeMaxDynamicSharedMemorySize, SMEM2);

    xproj_kernel<<<(B * T) / 64, 512>>>(input, Wih, bih, bhh);
    lstm_kernel<<<B, 512, SMEM2>>>(h0, c0, Whh, out);
}

// round 2
// speedup vs baseline: 1.2656x; 1.2656x over previous
#include <cuda_runtime.h>
#include <cstdint>
#include <cstddef>

// LSTM encoder: B=128, T=2048, I=64, H=128
// out[0 : B*H) = h_last ; out[B*H : B*H + B*T*H) = encoded
constexpr int B = 128;
constexpr int T = 2048;
constexpr int I = 64;
constexpr int H = 128;
constexpr int G = 4 * H;              // 512 gates
constexpr int KREG = 104;             // k-values of W_hh in registers (per gate)
constexpr int KSM  = H - KREG;        // 24 k-values in smem
constexpr int NP   = KREG / 2;        // 52 f32x2 pairs per gate
constexpr int NQ_SM = KSM / 4;        // 6 smem quads per gate

__device__ float g_xp[(size_t)B * T * G];   // 512 MB x_proj scratch

__device__ __forceinline__ void fma2(unsigned long long& d,
                                     unsigned long long a,
                                     unsigned long long b) {
    asm("fma.rn.f32x2 %0, %1, %2, %0;" : "+l"(d) : "l"(a), "l"(b));
}
__device__ __forceinline__ float pair_sum(unsigned long long v) {
    return __uint_as_float((unsigned)v) + __uint_as_float((unsigned)(v >> 32));
}
__device__ __forceinline__ float sig_f(float x) {
    return __fdividef(1.f, 1.f + __expf(-x));
}
__device__ __forceinline__ float tanh_f(float x) {
    // 1 - 2/(1+e^{2x}); saturates correctly at +-inf
    return 1.f - 2.f * __fdividef(1.f, 1.f + __expf(2.f * x));
}

// ---------------------------------------------------------------------------
// x_proj: 256 threads, 32 rows per CTA, thread t computes gates t and t+256.
// Input quad broadcast from smem feeds 4 fma2 (2 gates x 2 pairs) -> FMA-bound.
// ---------------------------------------------------------------------------
__global__ void __launch_bounds__(256) xproj_kernel(
    const float* __restrict__ in,     // [B*T, I]
    const float* __restrict__ Wih,    // [G, I]
    const float* __restrict__ bih,
    const float* __restrict__ bhh)
{
    __shared__ float in_s[32 * I];    // 8 KB
    const int t = threadIdx.x;
    const size_t row0 = (size_t)blockIdx.x * 32;

    {   // load 32x64 tile: 512 float4 by 256 threads
        const float4* src = (const float4*)(in + row0 * I);
        float4* dst = (float4*)in_s;
        dst[t]       = src[t];
        dst[t + 256] = src[t + 256];
    }

    const int gA = t, gB = t + 256;
    unsigned long long wA[32], wB[32];
    {
        const unsigned long long* ra = (const unsigned long long*)(Wih + (size_t)gA * I);
        const unsigned long long* rb = (const unsigned long long*)(Wih + (size_t)gB * I);
#pragma unroll
        for (int i = 0; i < 32; i++) { wA[i] = ra[i]; wB[i] = rb[i]; }
    }
    const float biasA = bih[gA] + bhh[gA];
    const float biasB = bih[gB] + bhh[gB];
    __syncthreads();

    float* outp = g_xp + row0 * G + gA;
#pragma unroll 2
    for (int r = 0; r < 32; r++) {
        const ulonglong2* ip = (const ulonglong2*)(in_s + r * I);
        unsigned long long a0 = 0ull, a1 = 0ull, b0 = 0ull, b1 = 0ull;
#pragma unroll
        for (int q = 0; q < 16; q++) {
            ulonglong2 iv = ip[q];
            fma2(a0, wA[2 * q],     iv.x);
            fma2(a1, wA[2 * q + 1], iv.y);
            fma2(b0, wB[2 * q],     iv.x);
            fma2(b1, wB[2 * q + 1], iv.y);
        }
        outp[(size_t)r * G]       = pair_sum(a0) + pair_sum(a1) + biasA;
        outp[(size_t)r * G + 256] = pair_sum(b0) + pair_sum(b1) + biasB;
    }
}

// ---------------------------------------------------------------------------
// Recurrence: 1 CTA per batch row, 256 threads, thread t owns gates t, t+256.
// W_hh[.,0:104] in registers (2x52 ull), W_hh[.,104:128] in smem k-major.
// Each broadcast h-quad LDS feeds 4 fma2. Two barriers per step.
// ---------------------------------------------------------------------------
__global__ void __launch_bounds__(256, 1) lstm_kernel(
    const float* __restrict__ h0,
    const float* __restrict__ c0,
    const float* __restrict__ Whh,   // [G, H]
    float* __restrict__ out)
{
    extern __shared__ float smem[];
    // Ws2[q][g] : ulonglong2 quad of W_hh[g][KREG+4q .. +3], q in [0,6), g in [0,512)
    ulonglong2* Ws2   = (ulonglong2*)smem;                    // 48 KB
    float*      h_s   = smem + NQ_SM * G * 4;                 // 128 floats (16B aligned)
    float*      gate_s= h_s + H;                              // 512 floats

    const int t0 = threadIdx.x;
    const int b  = blockIdx.x;
    const int gA = t0, gB = t0 + 256;

    {   // fill smem weight slice
        const ulonglong2* ra = (const ulonglong2*)(Whh + (size_t)gA * H + KREG);
        const ulonglong2* rb = (const ulonglong2*)(Whh + (size_t)gB * H + KREG);
#pragma unroll
        for (int q = 0; q < NQ_SM; q++) {
            Ws2[q * G + gA] = ra[q];
            Ws2[q * G + gB] = rb[q];
        }
    }

    unsigned long long wA[NP], wB[NP];
    {
        const unsigned long long* ra = (const unsigned long long*)(Whh + (size_t)gA * H);
        const unsigned long long* rb = (const unsigned long long*)(Whh + (size_t)gB * H);
#pragma unroll
        for (int i = 0; i < NP; i++) { wA[i] = ra[i]; wB[i] = rb[i]; }
    }

    float c = 0.f;
    if (t0 < H) {
        c = c0[b * H + t0];
        h_s[t0] = h0[b * H + t0];
    }

    const float* xp = g_xp + (size_t)b * T * G + gA;   // gB stream = xp + 256
    float xcA = xp[0],  xcB = xp[256];
    float xnA = xp[G],  xnB = xp[G + 256];

    __syncthreads();

    float* enc = out + (size_t)B * H + (size_t)b * T * H;

    for (int t = 0; t < T; t++) {
        float xfA = 0.f, xfB = 0.f;
        if (t < T - 2) {
            int off = (t + 2) * G;
            xfA = xp[off];
            xfB = xp[off + 256];
        }

        unsigned long long a0 = 0ull, a1 = 0ull, b0 = 0ull, b1 = 0ull;
        const ulonglong2* h2 = (const ulonglong2*)h_s;

        // register-resident k in [0, 104): 26 h-quads
#pragma unroll
        for (int q = 0; q < NP / 2; q++) {
            ulonglong2 hv = h2[q];
            fma2(a0, wA[2 * q],     hv.x);
            fma2(a1, wA[2 * q + 1], hv.y);
            fma2(b0, wB[2 * q],     hv.x);
            fma2(b1, wB[2 * q + 1], hv.y);
        }
        // smem-resident k in [104, 128): 6 h-quads
#pragma unroll
        for (int q = 0; q < NQ_SM; q++) {
            ulonglong2 hv = h2[NP / 2 + q];
            ulonglong2 wa = Ws2[q * G + gA];
            ulonglong2 wb = Ws2[q * G + gB];
            fma2(a0, wa.x, hv.x);
            fma2(a1, wa.y, hv.y);
            fma2(b0, wb.x, hv.x);
            fma2(b1, wb.y, hv.y);
        }

        gate_s[gA] = pair_sum(a0) + pair_sum(a1) + xcA;
        gate_s[gB] = pair_sum(b0) + pair_sum(b1) + xcB;
        xcA = xnA; xnA = xfA;
        xcB = xnB; xnB = xfB;
        __syncthreads();

        if (t0 < H) {
            float gi = gate_s[t0];
            float gf = gate_s[t0 + 128];
            float gg = gate_s[t0 + 256];
            float go = gate_s[t0 + 384];
            float ig = sig_f(gi);
            float fg = sig_f(gf);
            float og = sig_f(go);
            float gt = tanh_f(gg);
            c = fg * c + ig * gt;
            float hn = og * tanh_f(c);
            h_s[t0] = hn;
            enc[(size_t)t * H + t0] = hn;
            if (t == T - 1) out[b * H + t0] = hn;
        }
        __syncthreads();
    }
}

// ---------------------------------------------------------------------------
extern "C" void kernel_launch(void* const* d_in, const int* in_sizes, int n_in,
                              void* d_out, int out_size) {
    const float* input = (const float*)d_in[0];
    const float* h0    = (const float*)d_in[1];
    const float* c0    = (const float*)d_in[2];
    const float* Wih   = (const float*)d_in[3];
    const float* Whh   = (const float*)d_in[4];
    const float* bih   = (const float*)d_in[5];
    const float* bhh   = (const float*)d_in[6];
    float* out = (float*)d_out;

    constexpr int SMEM2 = (NQ_SM * G * 4 + H + G) * (int)sizeof(float); // 51712 B
    cudaFuncSetAttribute(lstm_kernel,
                         cudaFuncAttributeMaxDynamicSharedMemorySize, SMEM2);

    xproj_kernel<<<(B * T) / 32, 256>>>(input, Wih, bih, bhh);
    lstm_kernel<<<B, 256, SMEM2>>>(h0, c0, Whh, out);
}